// round 5
// baseline (speedup 1.0000x reference)
#include <cuda_runtime.h>
#include <math.h>
#include <stdint.h>

// ---------------------------------------------------------------------------
// BagAttentionNet forward. FFMA2 (f32x2) SIMT GEMM, M-paired accumulators,
// double-buffered smem pipeline (cp.async for W, reg-staged transpose for A).
// ---------------------------------------------------------------------------

#define NB 2048
#define CI 64
#define MR (NB * CI)          // 131072
#define TAU_F 0.95f

typedef unsigned long long ull;

// scratch (allocation-free rule: __device__ globals)
__device__ float g_h1[MR * 256];
__device__ float g_h2[MR * 256];
__device__ float g_h3[MR * 128];
__device__ float g_d1[MR * 128];
__device__ float g_d2[MR * 64];
__device__ float g_dd[MR];

__device__ __forceinline__ float act_apply(float v, int ACT) {
    if (ACT == 1) return v > 0.f ? v : 0.f;
    if (ACT == 2) return __fdividef(1.f, 1.f + __expf(-v));  // fast sigmoid
    return v;
}

__device__ __forceinline__ void cp_async16(void* s, const void* g) {
    unsigned sa = (unsigned)__cvta_generic_to_shared(s);
    asm volatile("cp.async.cg.shared.global [%0], [%1], 16;" :: "r"(sa), "l"(g));
}
#define CP_COMMIT() asm volatile("cp.async.commit_group;")
#define CP_WAIT0()  asm volatile("cp.async.wait_group 0;")

// C = act(A @ W + bias);  A: MxK row-major, W: KxN row-major, C: MxN.
// Per-thread tile: TM=16 rows (as 8 packed f32x2 row-pairs) x TN=4 cols.
// acc2[i2][j] lanes = rows (trow*16+2*i2, +1), col tcol*4+j.
template<int BM, int BN, int BK, int ACT>
__global__ void __launch_bounds__((BM / 16) * (BN / 4), 2)
gemm2(const float* __restrict__ A, const float* __restrict__ W,
      const float* __restrict__ bias, float* __restrict__ Cmat,
      int K, int N)
{
    constexpr int TM = 16, TN = 4;
    constexpr int RX = BN / TN, RY = BM / TM, THREADS = RX * RY;
    constexpr int GROUPS = THREADS / BM;          // threads per A-row group
    constexpr int KC  = BK / GROUPS;              // k-span staged per thread
    constexpr int AF4 = KC / 4;                   // float4 per thread for A
    constexpr int WC  = (BK * BN) / (4 * THREADS);// 16B chunks per thread for W
    constexpr int BMP = BM + 4;
    constexpr int N4  = BN / 4;

    extern __shared__ float smem[];
    float (*As)[BK][BMP] = (float (*)[BK][BMP])smem;
    float (*Ws)[BK][BN]  = (float (*)[BK][BN])(smem + 2 * BK * BMP);

    const int tid  = threadIdx.x;
    const int tcol = tid % RX;          // lane-linear within warp
    const int trow = tid / RX;          // warp-uniform
    const int brow = blockIdx.y * BM;
    const int bcol = blockIdx.x * BN;

    const int arow = tid % BM;
    const int akb  = (tid / BM) * KC;
    const float* Arow = A + (size_t)(brow + arow) * K + akb;

    ull acc2[8][TN];
#pragma unroll
    for (int i = 0; i < 8; i++)
#pragma unroll
        for (int j = 0; j < TN; j++) acc2[i][j] = 0ull;

    float4 areg[AF4];
    const int nt = K / BK;

    // ---- prologue: tile 0 ----
#pragma unroll
    for (int q = 0; q < AF4; q++)
        areg[q] = *(const float4*)(Arow + q * 4);
#pragma unroll
    for (int i = 0; i < WC; i++) {
        int idx = tid + i * THREADS;
        int k = idx / N4, n4 = idx % N4;
        cp_async16(&Ws[0][k][n4 * 4], W + (size_t)k * N + bcol + n4 * 4);
    }
    CP_COMMIT();
#pragma unroll
    for (int q = 0; q < AF4; q++) {
        As[0][akb + q * 4 + 0][arow] = areg[q].x;
        As[0][akb + q * 4 + 1][arow] = areg[q].y;
        As[0][akb + q * 4 + 2][arow] = areg[q].z;
        As[0][akb + q * 4 + 3][arow] = areg[q].w;
    }
    CP_WAIT0();
    __syncthreads();

    for (int t = 0; t < nt; t++) {
        const int cb = t & 1;
        const bool more = (t + 1 < nt);

        if (more) {
            const float* Ap = Arow + (size_t)(t + 1) * BK;
#pragma unroll
            for (int q = 0; q < AF4; q++)
                areg[q] = *(const float4*)(Ap + q * 4);
            const float* Wp = W + (size_t)(t + 1) * BK * N + bcol;
#pragma unroll
            for (int i = 0; i < WC; i++) {
                int idx = tid + i * THREADS;
                int k = idx / N4, n4 = idx % N4;
                cp_async16(&Ws[cb ^ 1][k][n4 * 4], Wp + (size_t)k * N + n4 * 4);
            }
            CP_COMMIT();
        }

#pragma unroll
        for (int k = 0; k < BK; k++) {
            float4 wv = *(const float4*)&Ws[cb][k][tcol * 4];
            ull wb0, wb1, wb2, wb3;
            asm("mov.b64 %0, {%1, %1};" : "=l"(wb0) : "f"(wv.x));
            asm("mov.b64 %0, {%1, %1};" : "=l"(wb1) : "f"(wv.y));
            asm("mov.b64 %0, {%1, %1};" : "=l"(wb2) : "f"(wv.z));
            asm("mov.b64 %0, {%1, %1};" : "=l"(wb3) : "f"(wv.w));
            const float* ab = &As[cb][k][trow * 16];
            ulonglong2 p01 = *(const ulonglong2*)(ab + 0);
            ulonglong2 p23 = *(const ulonglong2*)(ab + 4);
            ulonglong2 p45 = *(const ulonglong2*)(ab + 8);
            ulonglong2 p67 = *(const ulonglong2*)(ab + 12);
            ull ap[8] = {p01.x, p01.y, p23.x, p23.y, p45.x, p45.y, p67.x, p67.y};
#pragma unroll
            for (int i = 0; i < 8; i++) {
                asm("fma.rn.f32x2 %0, %1, %2, %0;" : "+l"(acc2[i][0]) : "l"(ap[i]), "l"(wb0));
                asm("fma.rn.f32x2 %0, %1, %2, %0;" : "+l"(acc2[i][1]) : "l"(ap[i]), "l"(wb1));
                asm("fma.rn.f32x2 %0, %1, %2, %0;" : "+l"(acc2[i][2]) : "l"(ap[i]), "l"(wb2));
                asm("fma.rn.f32x2 %0, %1, %2, %0;" : "+l"(acc2[i][3]) : "l"(ap[i]), "l"(wb3));
            }
        }

        if (more) {
#pragma unroll
            for (int q = 0; q < AF4; q++) {
                As[cb ^ 1][akb + q * 4 + 0][arow] = areg[q].x;
                As[cb ^ 1][akb + q * 4 + 1][arow] = areg[q].y;
                As[cb ^ 1][akb + q * 4 + 2][arow] = areg[q].z;
                As[cb ^ 1][akb + q * 4 + 3][arow] = areg[q].w;
            }
            CP_WAIT0();
        }
        __syncthreads();
    }

    // ---- epilogue ----
    const int colb = bcol + tcol * 4;
    float4 bv = *(const float4*)(bias + colb);
#pragma unroll
    for (int i2 = 0; i2 < 8; i2++) {
        int row0 = brow + trow * 16 + 2 * i2;
        float e0, o0, e1, o1, e2, o2, e3, o3;
        asm("mov.b64 {%0, %1}, %2;" : "=f"(e0), "=f"(o0) : "l"(acc2[i2][0]));
        asm("mov.b64 {%0, %1}, %2;" : "=f"(e1), "=f"(o1) : "l"(acc2[i2][1]));
        asm("mov.b64 {%0, %1}, %2;" : "=f"(e2), "=f"(o2) : "l"(acc2[i2][2]));
        asm("mov.b64 {%0, %1}, %2;" : "=f"(e3), "=f"(o3) : "l"(acc2[i2][3]));
        float4 re, ro;
        re.x = act_apply(e0 + bv.x, ACT); re.y = act_apply(e1 + bv.y, ACT);
        re.z = act_apply(e2 + bv.z, ACT); re.w = act_apply(e3 + bv.w, ACT);
        ro.x = act_apply(o0 + bv.x, ACT); ro.y = act_apply(o1 + bv.y, ACT);
        ro.z = act_apply(o2 + bv.z, ACT); ro.w = act_apply(o3 + bv.w, ACT);
        *(float4*)(Cmat + (size_t)row0 * N + colb)       = re;
        *(float4*)(Cmat + (size_t)(row0 + 1) * N + colb) = ro;
    }
}

// d[r] = d2[r,:] . D3 + db3   (K = 64), one warp per row
__global__ void dot_kernel(const float* __restrict__ d2, const float* __restrict__ D3,
                           const float* __restrict__ db3, float* __restrict__ dd)
{
    int gw   = (blockIdx.x * blockDim.x + threadIdx.x) >> 5;
    int lane = threadIdx.x & 31;
    if (gw >= MR) return;
    const float* row = d2 + (size_t)gw * 64;
    float s = row[lane] * D3[lane] + row[lane + 32] * D3[lane + 32];
#pragma unroll
    for (int o = 16; o > 0; o >>= 1) s += __shfl_down_sync(0xffffffffu, s, o);
    if (lane == 0) dd[gw] = s + db3[0];
}

// Per-bag: gumbel softmax, top-20 keep (stable), re-softmax, aggregate, project.
// Precise expf/logf here: this kernel determines the hard keep-selection.
__global__ void __launch_bounds__(128)
final_kernel(const float* __restrict__ dd, const float* __restrict__ m,
             const float* __restrict__ u, const float* __restrict__ h3,
             const float* __restrict__ E, const float* __restrict__ eb,
             float* __restrict__ out_w, float* __restrict__ out_s)
{
    const int bag = blockIdx.x;
    const int t   = threadIdx.x;   // 128 threads

    __shared__ float sm[64];
    __shared__ float wf[64];
    __shared__ float red[128];

    float z = 0.f;
    if (t < 64) {
        float logit = m[bag * 64 + t] * dd[bag * 64 + t];
        float uu = u[bag * 64 + t];
        float g = -logf(-logf(uu));
        z = (logit + g) / TAU_F;
    }

    red[t] = (t < 64) ? z : -INFINITY;
    __syncthreads();
#pragma unroll
    for (int s = 64; s >= 1; s >>= 1) {
        if (t < s) red[t] = fmaxf(red[t], red[t + s]);
        __syncthreads();
    }
    float zmax = red[0];
    __syncthreads();

    float e = (t < 64) ? expf(z - zmax) : 0.f;
    red[t] = e;
    __syncthreads();
#pragma unroll
    for (int s = 64; s >= 1; s >>= 1) {
        if (t < s) red[t] += red[t + s];
        __syncthreads();
    }
    float psum = red[0];
    __syncthreads();

    float p = e / psum;
    if (t < 64) sm[t] = p;
    __syncthreads();

    int keep = 0;
    if (t < 64) {
        int pos = 0;
#pragma unroll 8
        for (int j = 0; j < 64; j++) {
            float o = sm[j];
            pos += (o < p) || (o == p && j < t);
        }
        keep = (pos >= 44);
    }

    red[t] = (t < 64 && keep) ? p : -INFINITY;
    __syncthreads();
#pragma unroll
    for (int s = 64; s >= 1; s >>= 1) {
        if (t < s) red[t] = fmaxf(red[t], red[t + s]);
        __syncthreads();
    }
    float m2 = red[0];
    __syncthreads();

    float e2 = (t < 64 && keep) ? expf(p - m2) : 0.f;
    red[t] = e2;
    __syncthreads();
#pragma unroll
    for (int s = 64; s >= 1; s >>= 1) {
        if (t < s) red[t] += red[t + s];
        __syncthreads();
    }
    float s2 = red[0];
    __syncthreads();

    float wfin = (t < 64 && keep) ? (e2 / s2) : 0.f;
    if (t < 64) {
        wf[t] = wfin;
        out_w[bag * 64 + t] = wfin;
    }
    __syncthreads();

    const float* hb = h3 + (size_t)bag * 64 * 128;
    float agg = 0.f;
#pragma unroll 8
    for (int c = 0; c < 64; c++) agg += wf[c] * hb[c * 128 + t];
    red[t] = agg * E[t];
    __syncthreads();
#pragma unroll
    for (int s = 64; s >= 1; s >>= 1) {
        if (t < s) red[t] += red[t + s];
        __syncthreads();
    }
    if (t == 0) out_s[bag] = red[0] + eb[0];
}

template<int BM, int BN, int BK>
static inline int smem_bytes() { return (2 * BK * (BM + 4) + 2 * BK * BN) * 4; }

extern "C" void kernel_launch(void* const* d_in, const int* in_sizes, int n_in,
                              void* d_out, int out_size)
{
    const float* x   = (const float*)d_in[0];
    const float* m   = (const float*)d_in[1];
    const float* u   = (const float*)d_in[2];
    const float* W1  = (const float*)d_in[3];
    const float* b1  = (const float*)d_in[4];
    const float* W2  = (const float*)d_in[5];
    const float* b2  = (const float*)d_in[6];
    const float* W3  = (const float*)d_in[7];
    const float* b3  = (const float*)d_in[8];
    const float* D1  = (const float*)d_in[9];
    const float* db1 = (const float*)d_in[10];
    const float* D2  = (const float*)d_in[11];
    const float* db2 = (const float*)d_in[12];
    const float* D3  = (const float*)d_in[13];
    const float* db3 = (const float*)d_in[14];
    const float* E   = (const float*)d_in[15];
    const float* eb  = (const float*)d_in[16];
    float* out = (float*)d_out;

    float *h1, *h2, *h3, *d1, *d2, *dd;
    cudaGetSymbolAddress((void**)&h1, g_h1);
    cudaGetSymbolAddress((void**)&h2, g_h2);
    cudaGetSymbolAddress((void**)&h3, g_h3);
    cudaGetSymbolAddress((void**)&d1, g_d1);
    cudaGetSymbolAddress((void**)&d2, g_d2);
    cudaGetSymbolAddress((void**)&dd, g_dd);

    constexpr int S128 = (2 * 32 * 132 + 2 * 32 * 128) * 4;   // 66.6 KB
    constexpr int S64  = (2 * 16 * 132 + 2 * 16 * 64) * 4;    // 25.1 KB

    static int attr_done = 0;
    if (!attr_done) {
        cudaFuncSetAttribute(gemm2<128,128,32,1>, cudaFuncAttributeMaxDynamicSharedMemorySize, S128);
        cudaFuncSetAttribute(gemm2<128,128,32,2>, cudaFuncAttributeMaxDynamicSharedMemorySize, S128);
        cudaFuncSetAttribute(gemm2<128, 64,16,2>, cudaFuncAttributeMaxDynamicSharedMemorySize, S64);
        attr_done = 1;
    }

    // h1 = relu(x @ W1 + b1)             131072 x 512 x 256
    gemm2<128,128,32,1><<<dim3(2, MR/128), 256, S128>>>(x,  W1, b1, h1, 512, 256);
    // h2 = relu(h1 @ W2 + b2)            131072 x 256 x 256
    gemm2<128,128,32,1><<<dim3(2, MR/128), 256, S128>>>(h1, W2, b2, h2, 256, 256);
    // h3 = relu(h2 @ W3 + b3)            131072 x 256 x 128
    gemm2<128,128,32,1><<<dim3(1, MR/128), 256, S128>>>(h2, W3, b3, h3, 256, 128);
    // d1 = sigmoid(h3 @ D1 + db1)        131072 x 128 x 128
    gemm2<128,128,32,2><<<dim3(1, MR/128), 256, S128>>>(h3, D1, db1, d1, 128, 128);
    // d2 = sigmoid(d1 @ D2 + db2)        131072 x 128 x 64
    gemm2<128, 64,16,2><<<dim3(1, MR/128), 128, S64>>>(d1, D2, db2, d2, 128, 64);
    // dd = d2 @ D3 + db3
    dot_kernel<<<MR / 8, 256>>>(d2, D3, db3, dd);
    // w + out
    final_kernel<<<NB, 128>>>(dd, m, u, h3, E, eb, out, out + MR);
}